// round 15
// baseline (speedup 1.0000x reference)
#include <cuda_runtime.h>
#include <cuda_fp16.h>
#include <cstdint>
#include <math.h>

// ---------------- problem constants ----------------------------------------
#define T_TOKENS 1024
#define NUM_E    8
#define HID      4096
#define INTER    4096
#define N1       (2*INTER)

#define BM 128
#define KCH 64                  // K elems per chunk (64 fp16 = 128 bytes/row)
#define NCHUNK (HID/KCH)        // 64
#define NTHREADS 512

#define ROWS_CAP  3072
#define ROW_TILES (ROWS_CAP/BM) // 24
#define G1_BLOCKS (ROW_TILES * (INTER/128))  // 768  (nTile covers 128 gate + 128 up)
#define G2_BLOCKS (ROW_TILES * (HID/256))    // 384  (nTile covers 256 out cols)

// smem: A 3 x 16KB, B 2 x 32KB
#define ABASE 0
#define BBASE (3*16384)
#define SMEM_BYTES (BBASE + 2*32768 + 128)

// ---------------- device scratch --------------------------------------------
__device__ int    g_row_expert[ROW_TILES];
__device__ int    g_perm_tok[ROWS_CAP];
__device__ float  g_perm_w[ROWS_CAP];
__device__ int    g_nrows;
__device__ int    g_done[ROW_TILES];
__device__ __half g_Xh[(size_t)T_TOKENS * HID];          // 8 MB
__device__ __half g_h[(size_t)ROWS_CAP * INTER];         // 25 MB

// ---------------- PTX helpers -----------------------------------------------
__device__ __forceinline__ uint32_t smem_u32(const void* p) {
    uint32_t a;
    asm("{ .reg .u64 t; cvta.to.shared.u64 t, %1; cvt.u32.u64 %0, t; }" : "=r"(a) : "l"(p));
    return a;
}
__device__ __forceinline__ void cp16(uint32_t dst, const void* src, int srcsize) {
    asm volatile("cp.async.cg.shared.global [%0], [%1], 16, %2;\n"
                 :: "r"(dst), "l"(src), "r"(srcsize));
}
#define CP_COMMIT() asm volatile("cp.async.commit_group;" ::: "memory")
#define CP_WAIT1()  asm volatile("cp.async.wait_group 1;" ::: "memory")
#define CP_WAIT0()  asm volatile("cp.async.wait_group 0;" ::: "memory")

#define LDSM4(d0,d1,d2,d3,a) \
    asm volatile("ldmatrix.sync.aligned.m8n8.x4.shared.b16 {%0,%1,%2,%3}, [%4];" \
        : "=r"(d0), "=r"(d1), "=r"(d2), "=r"(d3) : "r"(a))

__device__ __forceinline__ void mma_f16(float* c, uint32_t a0, uint32_t a1,
                                        uint32_t a2, uint32_t a3,
                                        uint32_t b0, uint32_t b1) {
    asm volatile(
        "mma.sync.aligned.m16n8k16.row.col.f32.f16.f16.f32 "
        "{%0,%1,%2,%3}, {%4,%5,%6,%7}, {%8,%9}, {%0,%1,%2,%3};"
        : "+f"(c[0]), "+f"(c[1]), "+f"(c[2]), "+f"(c[3])
        : "r"(a0), "r"(a1), "r"(a2), "r"(a3), "r"(b0), "r"(b1));
}

__device__ __forceinline__ uint2 cvt4(float4 v) {
    __half2 h0 = __floats2half2_rn(v.x, v.y);
    __half2 h1 = __floats2half2_rn(v.z, v.w);
    uint2 u;
    u.x = *reinterpret_cast<uint32_t*>(&h0);
    u.y = *reinterpret_cast<uint32_t*>(&h1);
    return u;
}

// ---------------- small kernels ---------------------------------------------
__global__ void k_init(float4* __restrict__ out4, const float4* __restrict__ x4) {
    int idx = blockIdx.x * blockDim.x + threadIdx.x;
    const int n4 = (T_TOKENS * HID) / 4;
    if (idx < n4) {
        out4[idx] = make_float4(0.f, 0.f, 0.f, 0.f);
        ((uint2*)g_Xh)[idx] = cvt4(x4[idx]);
    }
}

__global__ void k_prep(const float* __restrict__ logits) {
    __shared__ int   s_cnt[NUM_E];
    __shared__ int   s_pos[NUM_E];
    __shared__ int   s_e[2 * T_TOKENS];
    __shared__ float s_w[2 * T_TOKENS];

    const int tid = threadIdx.x;
    if (tid < NUM_E)     s_cnt[tid] = 0;
    if (tid < ROW_TILES) g_done[tid] = 0;
    for (int i = tid; i < ROWS_CAP; i += 1024) g_perm_tok[i] = -1;
    __syncthreads();

    {
        const int t = tid;
        float l[NUM_E];
#pragma unroll
        for (int e = 0; e < NUM_E; e++) l[e] = logits[t * NUM_E + e];
        int i0 = 0;
#pragma unroll
        for (int e = 1; e < NUM_E; e++) if (l[e] > l[i0]) i0 = e;
        int i1 = -1; float l1 = -1e30f;
#pragma unroll
        for (int e = 0; e < NUM_E; e++) {
            if (e == i0) continue;
            if (i1 < 0 || l[e] > l1) { i1 = e; l1 = l[e]; }
        }
        float w0 = 1.f / (1.f + expf(l1 - l[i0]));
        s_e[2*t]   = i0;  s_w[2*t]   = w0;
        s_e[2*t+1] = i1;  s_w[2*t+1] = 1.f - w0;
        atomicAdd(&s_cnt[i0], 1);
        atomicAdd(&s_cnt[i1], 1);
    }
    __syncthreads();

    if (tid == 0) {
        int off = 0;
        for (int e = 0; e < NUM_E; e++) {
            s_pos[e] = off;
            int padded = ((s_cnt[e] + BM - 1) / BM) * BM;
            int t0 = off / BM, t1 = (off + padded) / BM;
            for (int t = t0; t < t1; t++) g_row_expert[t] = e;
            off += padded;
        }
        g_nrows = off;
        for (int t = off / BM; t < ROW_TILES; t++) g_row_expert[t] = 0;
    }
    __syncthreads();

    for (int s = tid; s < 2 * T_TOKENS; s += 1024) {
        int e = s_e[s];
        int p = atomicAdd(&s_pos[e], 1);
        g_perm_tok[p] = s >> 1;
        g_perm_w[p]   = s_w[s];
    }
}

// ============================================================================
// Fused MoE GEMM kernel, 512 threads (16 warps), wide N-tiles.
//   blocks [0, G1) : GEMM1 (+SiLU) 128m x (128 gate + 128 up) -> g_h
//   blocks [G1, G1+G2) : GEMM2 128m x 256n -> out (spins on g_done==32)
// Warp grid 4m x 4n. G1 warp tile 32m x 32n per matrix; G2 32m x 64n.
// ============================================================================
__global__ __launch_bounds__(NTHREADS, 1)
void k_moe(const float* __restrict__ W13f, const float* __restrict__ W2f,
           float* __restrict__ out) {
    extern __shared__ char dsm[];
    __shared__ int   toks[BM];
    __shared__ float wts[BM];

    const int tid  = threadIdx.x;
    const int bid  = blockIdx.x;
    const int lane = tid & 31, wid = tid >> 5;
    char* sb = (char*)(((uintptr_t)dsm + 127) & ~(uintptr_t)127);
    const uint32_t sbase = smem_u32(sb);

    const int lrow = lane & 15;
    const uint32_t xm   = (lane & 7) << 4;
    const uint32_t koff = (lane >> 4) * 16;

    if (bid < G1_BLOCKS) {
        // ==================== GEMM1 (+fused SiLU) ====================
        const int rowTile = bid >> 5, nTile = bid & 31;   // nTile: 128-wide
        if (rowTile * BM >= g_nrows) return;

        if (tid < BM) toks[tid] = g_perm_tok[rowTile * BM + tid];
        __syncthreads();

        const int e = g_row_expert[rowTile];
        const float* Wg = W13f + (size_t)e * N1 * HID + (size_t)(nTile * 128) * HID;

        auto fillA = [&](int st, int c) {
            const int k0 = c * KCH;
#pragma unroll
            for (int j = 0; j < 2; j++) {
                int idx = tid + j * NTHREADS;
                int row = idx >> 3, seg = idx & 7;
                int tok = toks[row];
                uint32_t dst = sbase + ABASE + st * 16384
                             + row * 128 + ((seg * 16) ^ ((row & 7) << 4));
                cp16(dst, g_Xh + (size_t)(tok < 0 ? 0 : tok) * HID + k0 + seg * 8,
                     tok < 0 ? 0 : 16);
            }
            CP_COMMIT();
        };

        // B: rows 0-127 gate, 128-255 up. 4096 f4 -> 8 per thread (cvt at LDG).
        uint2 hreg[8];
        auto ldgB = [&](int c) {
            const int k0 = c * KCH;
#pragma unroll
            for (int j = 0; j < 8; j++) {
                int idx = tid + j * NTHREADS;
                int row = idx >> 4, f4 = idx & 15;
                int grow = (row < 128) ? row : (INTER + row - 128);
                hreg[j] = cvt4(__ldg((const float4*)(Wg + (size_t)grow * HID + k0) + f4));
            }
        };
        auto stsB = [&](int st) {
#pragma unroll
            for (int j = 0; j < 8; j++) {
                int idx = tid + j * NTHREADS;
                int row = idx >> 4, f4 = idx & 15;
                int seg = f4 >> 1;
                uint32_t off = BBASE + st * 32768 + row * 128
                             + ((seg * 16) ^ ((row & 7) << 4)) + (f4 & 1) * 8;
                *(uint2*)(sb + off) = hreg[j];
            }
        };

        ldgB(0);
        fillA(0, 0);
        fillA(1, 1);
        stsB(0);
        ldgB(1);

        // warp grid 4m x 4n; warp tile 32m x 32n per matrix
        const int wm = (wid & 3) * 32, wn = (wid >> 2) * 32;

        float cg[2][4][4], cu[2][4][4];
#pragma unroll
        for (int mt = 0; mt < 2; mt++)
#pragma unroll
            for (int nt = 0; nt < 4; nt++)
#pragma unroll
                for (int v = 0; v < 4; v++) { cg[mt][nt][v] = 0.f; cu[mt][nt][v] = 0.f; }

        for (int i = 0; i < NCHUNK; i++) {
            const int st = i & 1;
            if (i < NCHUNK - 1) { CP_WAIT1(); } else { CP_WAIT0(); }
            __syncthreads();
            if (i + 1 < NCHUNK) stsB(st ^ 1);
            if (i + 2 < NCHUNK) { ldgB(i + 2); fillA((i + 2) % 3, i + 2); }

            const uint32_t Ast = sbase + ABASE + (i % 3) * 16384;
            const uint32_t Bst = sbase + BBASE + st * 32768;
#pragma unroll
            for (int ks = 0; ks < 4; ks++) {
                const uint32_t kb = (uint32_t)(ks * 32 + koff) ^ xm;
                uint32_t a[2][4], bg[2][4], bu[2][4];
#pragma unroll
                for (int mt = 0; mt < 2; mt++)
                    LDSM4(a[mt][0], a[mt][1], a[mt][2], a[mt][3],
                          Ast + (wm + mt * 16 + lrow) * 128 + kb);
#pragma unroll
                for (int g = 0; g < 2; g++) {
                    LDSM4(bg[g][0], bg[g][1], bg[g][2], bg[g][3],
                          Bst + (wn + g * 16 + lrow) * 128 + kb);
                    LDSM4(bu[g][0], bu[g][1], bu[g][2], bu[g][3],
                          Bst + 16384 + (wn + g * 16 + lrow) * 128 + kb);
                }
#pragma unroll
                for (int mt = 0; mt < 2; mt++)
#pragma unroll
                    for (int nt = 0; nt < 4; nt++) {
                        int g = nt >> 1, s = nt & 1;
                        mma_f16(cg[mt][nt], a[mt][0], a[mt][1], a[mt][2], a[mt][3],
                                bg[g][s], bg[g][2 + s]);
                        mma_f16(cu[mt][nt], a[mt][0], a[mt][1], a[mt][2], a[mt][3],
                                bu[g][s], bu[g][2 + s]);
                    }
            }
        }

        // epilogue: silu(gate)*up -> g_h (fp16)
        const int r0 = rowTile * BM + wm + lane / 4;
        const int cbase = nTile * 128 + wn + (lane % 4) * 2;
#pragma unroll
        for (int mt = 0; mt < 2; mt++) {
#pragma unroll
            for (int nt = 0; nt < 4; nt++) {
                __half* h0 = g_h + (size_t)(r0 + mt * 16) * INTER + cbase + nt * 8;
                __half* h1 = h0 + 8 * INTER;
                float g0 = cg[mt][nt][0], g1 = cg[mt][nt][1];
                float g2 = cg[mt][nt][2], g3 = cg[mt][nt][3];
                float v0 = g0 / (1.f + __expf(-g0)) * cu[mt][nt][0];
                float v1 = g1 / (1.f + __expf(-g1)) * cu[mt][nt][1];
                float v2 = g2 / (1.f + __expf(-g2)) * cu[mt][nt][2];
                float v3 = g3 / (1.f + __expf(-g3)) * cu[mt][nt][3];
                *(__half2*)h0 = __floats2half2_rn(v0, v1);
                *(__half2*)h1 = __floats2half2_rn(v2, v3);
            }
        }
        // publish
        __threadfence();
        __syncthreads();
        if (tid == 0) atomicAdd(&g_done[rowTile], 1);

    } else {
        // ==================== GEMM2 ====================
        const int b2 = bid - G1_BLOCKS;
        const int rowTile = b2 >> 4, nTile = b2 & 15;     // nTile: 256-wide
        if (rowTile * BM >= g_nrows) return;

        if (tid < BM) {
            toks[tid] = g_perm_tok[rowTile * BM + tid];
            wts[tid]  = g_perm_w[rowTile * BM + tid];
        }
        if (tid == 0) {
            while (*(volatile int*)&g_done[rowTile] < 32) __nanosleep(128);
        }
        __syncthreads();
        __threadfence();

        const int e = g_row_expert[rowTile];
        const __half* A = g_h + (size_t)(rowTile * BM) * INTER;
        const float*  W = W2f + (size_t)e * HID * INTER + (size_t)(nTile * 256) * INTER;

        auto fillA = [&](int st, int c) {
            const int k0 = c * KCH;
#pragma unroll
            for (int j = 0; j < 2; j++) {
                int idx = tid + j * NTHREADS;
                int row = idx >> 3, seg = idx & 7;
                uint32_t dst = sbase + ABASE + st * 16384
                             + row * 128 + ((seg * 16) ^ ((row & 7) << 4));
                cp16(dst, A + (size_t)row * INTER + k0 + seg * 8, 16);
            }
            CP_COMMIT();
        };

        uint2 hreg[8];
        auto ldgB = [&](int c) {
            const int k0 = c * KCH;
#pragma unroll
            for (int j = 0; j < 8; j++) {
                int idx = tid + j * NTHREADS;
                int row = idx >> 4, f4 = idx & 15;
                hreg[j] = cvt4(__ldg((const float4*)(W + (size_t)row * INTER + k0) + f4));
            }
        };
        auto stsB = [&](int st) {
#pragma unroll
            for (int j = 0; j < 8; j++) {
                int idx = tid + j * NTHREADS;
                int row = idx >> 4, f4 = idx & 15;
                int seg = f4 >> 1;
                uint32_t off = BBASE + st * 32768 + row * 128
                             + ((seg * 16) ^ ((row & 7) << 4)) + (f4 & 1) * 8;
                *(uint2*)(sb + off) = hreg[j];
            }
        };

        ldgB(0);
        fillA(0, 0);
        fillA(1, 1);
        stsB(0);
        ldgB(1);

        // warp grid 4m x 4n; warp tile 32m x 64n
        const int wm = (wid & 3) * 32, wn = (wid >> 2) * 64;

        float c[2][8][4];
#pragma unroll
        for (int mt = 0; mt < 2; mt++)
#pragma unroll
            for (int nt = 0; nt < 8; nt++)
#pragma unroll
                for (int v = 0; v < 4; v++) c[mt][nt][v] = 0.f;

        for (int i = 0; i < NCHUNK; i++) {
            const int st = i & 1;
            if (i < NCHUNK - 1) { CP_WAIT1(); } else { CP_WAIT0(); }
            __syncthreads();
            if (i + 1 < NCHUNK) stsB(st ^ 1);
            if (i + 2 < NCHUNK) { ldgB(i + 2); fillA((i + 2) % 3, i + 2); }

            const uint32_t Ast = sbase + ABASE + (i % 3) * 16384;
            const uint32_t Bst = sbase + BBASE + st * 32768;
#pragma unroll
            for (int ks = 0; ks < 4; ks++) {
                const uint32_t kb = (uint32_t)(ks * 32 + koff) ^ xm;
                uint32_t a[2][4], b[4][4];
#pragma unroll
                for (int mt = 0; mt < 2; mt++)
                    LDSM4(a[mt][0], a[mt][1], a[mt][2], a[mt][3],
                          Ast + (wm + mt * 16 + lrow) * 128 + kb);
#pragma unroll
                for (int g = 0; g < 4; g++)
                    LDSM4(b[g][0], b[g][1], b[g][2], b[g][3],
                          Bst + (wn + g * 16 + lrow) * 128 + kb);
#pragma unroll
                for (int mt = 0; mt < 2; mt++)
#pragma unroll
                    for (int nt = 0; nt < 8; nt++) {
                        int g = nt >> 1, s = nt & 1;
                        mma_f16(c[mt][nt], a[mt][0], a[mt][1], a[mt][2], a[mt][3],
                                b[g][s], b[g][2 + s]);
                    }
            }
        }

        // epilogue: weighted atomic combine (exactly 2 contributions per token;
        // 2-operand fp add onto zeroed buffer is order-invariant -> deterministic)
        const int cbase = nTile * 256 + wn + (lane % 4) * 2;
#pragma unroll
        for (int mt = 0; mt < 2; mt++) {
            const int rl0 = wm + mt * 16 + lane / 4;
            const int tok0 = toks[rl0],     tok1 = toks[rl0 + 8];
            const float w0 = wts[rl0],      w1 = wts[rl0 + 8];
            float* o0 = (tok0 >= 0) ? out + (size_t)tok0 * HID + cbase : nullptr;
            float* o1 = (tok1 >= 0) ? out + (size_t)tok1 * HID + cbase : nullptr;
#pragma unroll
            for (int nt = 0; nt < 8; nt++) {
                if (tok0 >= 0) {
                    atomicAdd(o0 + nt * 8,     w0 * c[mt][nt][0]);
                    atomicAdd(o0 + nt * 8 + 1, w0 * c[mt][nt][1]);
                }
                if (tok1 >= 0) {
                    atomicAdd(o1 + nt * 8,     w1 * c[mt][nt][2]);
                    atomicAdd(o1 + nt * 8 + 1, w1 * c[mt][nt][3]);
                }
            }
        }
    }
}

// ---------------- launch -----------------------------------------------------
extern "C" void kernel_launch(void* const* d_in, const int* in_sizes, int n_in,
                              void* d_out, int out_size) {
    const float* X      = (const float*)d_in[0];
    const float* logits = (const float*)d_in[1];
    const float* W13    = (const float*)d_in[2];
    const float* W2     = (const float*)d_in[3];
    float* out = (float*)d_out;

    cudaFuncSetAttribute(k_moe, cudaFuncAttributeMaxDynamicSharedMemorySize, SMEM_BYTES);

    k_init<<<4096, 256>>>((float4*)out, (const float4*)X);
    k_prep<<<1, 1024>>>(logits);
    k_moe<<<G1_BLOCKS + G2_BLOCKS, NTHREADS, SMEM_BYTES>>>(W13, W2, out);
}

// round 16
// speedup vs baseline: 1.2017x; 1.2017x over previous
#include <cuda_runtime.h>
#include <cuda_fp16.h>
#include <cstdint>
#include <math.h>

// ---------------- problem constants ----------------------------------------
#define T_TOKENS 1024
#define NUM_E    8
#define HID      4096
#define INTER    4096
#define N1       (2*INTER)

#define BM 128
#define KCH 64                  // K elems per chunk (64 fp16 = 128 bytes/row)
#define NCHUNK (HID/KCH)        // 64
#define NTHREADS 512

#define ROWS_CAP  3072
#define ROW_TILES (ROWS_CAP/BM) // 24
#define G1_BLOCKS (ROW_TILES * (INTER/64))   // 1536
#define G2_BLOCKS (ROW_TILES * (HID/128))    // 768

// ---------------- device scratch --------------------------------------------
__device__ int    g_row_expert[ROW_TILES];
__device__ int    g_perm_tok[ROWS_CAP];
__device__ float  g_perm_w[ROWS_CAP];
__device__ int    g_nrows;
__device__ int    g_done[ROW_TILES];
__device__ __half g_Xh[(size_t)T_TOKENS * HID];          // 8 MB
__device__ __half g_h[(size_t)ROWS_CAP * INTER];         // 25 MB

// ---------------- PTX helpers -----------------------------------------------
__device__ __forceinline__ uint32_t smem_u32(const void* p) {
    uint32_t a;
    asm("{ .reg .u64 t; cvta.to.shared.u64 t, %1; cvt.u32.u64 %0, t; }" : "=r"(a) : "l"(p));
    return a;
}
__device__ __forceinline__ void cp16(uint32_t dst, const void* src, int srcsize) {
    asm volatile("cp.async.cg.shared.global [%0], [%1], 16, %2;\n"
                 :: "r"(dst), "l"(src), "r"(srcsize));
}
#define CP_COMMIT() asm volatile("cp.async.commit_group;" ::: "memory")
#define CP_WAIT1()  asm volatile("cp.async.wait_group 1;" ::: "memory")
#define CP_WAIT0()  asm volatile("cp.async.wait_group 0;" ::: "memory")

#define LDSM4(d0,d1,d2,d3,a) \
    asm volatile("ldmatrix.sync.aligned.m8n8.x4.shared.b16 {%0,%1,%2,%3}, [%4];" \
        : "=r"(d0), "=r"(d1), "=r"(d2), "=r"(d3) : "r"(a))

__device__ __forceinline__ void mma_f16(float* c, uint32_t a0, uint32_t a1,
                                        uint32_t a2, uint32_t a3,
                                        uint32_t b0, uint32_t b1) {
    asm volatile(
        "mma.sync.aligned.m16n8k16.row.col.f32.f16.f16.f32 "
        "{%0,%1,%2,%3}, {%4,%5,%6,%7}, {%8,%9}, {%0,%1,%2,%3};"
        : "+f"(c[0]), "+f"(c[1]), "+f"(c[2]), "+f"(c[3])
        : "r"(a0), "r"(a1), "r"(a2), "r"(a3), "r"(b0), "r"(b1));
}

__device__ __forceinline__ uint2 cvt4(float4 v) {
    __half2 h0 = __floats2half2_rn(v.x, v.y);
    __half2 h1 = __floats2half2_rn(v.z, v.w);
    uint2 u;
    u.x = *reinterpret_cast<uint32_t*>(&h0);
    u.y = *reinterpret_cast<uint32_t*>(&h1);
    return u;
}

// ---------------- setup: init (blocks 0-1023) + prep (block 1024) ------------
__global__ void k_setup(float4* __restrict__ out4, const float4* __restrict__ x4,
                        const float* __restrict__ logits) {
    if (blockIdx.x < 1024) {
        // zero out + convert X fp32->fp16 (1M float4 over 1024x1024 threads)
        int idx = blockIdx.x * 1024 + threadIdx.x;
        out4[idx] = make_float4(0.f, 0.f, 0.f, 0.f);
        ((uint2*)g_Xh)[idx] = cvt4(x4[idx]);
        return;
    }

    // ---- prep block: route (top-2 softmax) -> padded scan -> scatter ----
    __shared__ int   s_cnt[NUM_E];
    __shared__ int   s_pos[NUM_E];
    __shared__ int   s_e[2 * T_TOKENS];
    __shared__ float s_w[2 * T_TOKENS];

    const int tid = threadIdx.x;
    if (tid < NUM_E)     s_cnt[tid] = 0;
    if (tid < ROW_TILES) g_done[tid] = 0;
    for (int i = tid; i < ROWS_CAP; i += 1024) g_perm_tok[i] = -1;
    __syncthreads();

    // route: one thread per token
    {
        const int t = tid;
        float l[NUM_E];
#pragma unroll
        for (int e = 0; e < NUM_E; e++) l[e] = logits[t * NUM_E + e];
        int i0 = 0;
#pragma unroll
        for (int e = 1; e < NUM_E; e++) if (l[e] > l[i0]) i0 = e;
        int i1 = -1; float l1 = -1e30f;
#pragma unroll
        for (int e = 0; e < NUM_E; e++) {
            if (e == i0) continue;
            if (i1 < 0 || l[e] > l1) { i1 = e; l1 = l[e]; }
        }
        float w0 = 1.f / (1.f + expf(l1 - l[i0]));
        s_e[2*t]   = i0;  s_w[2*t]   = w0;
        s_e[2*t+1] = i1;  s_w[2*t+1] = 1.f - w0;
        atomicAdd(&s_cnt[i0], 1);
        atomicAdd(&s_cnt[i1], 1);
    }
    __syncthreads();

    // scan (serial, tiny)
    if (tid == 0) {
        int off = 0;
        for (int e = 0; e < NUM_E; e++) {
            s_pos[e] = off;
            int padded = ((s_cnt[e] + BM - 1) / BM) * BM;
            int t0 = off / BM, t1 = (off + padded) / BM;
            for (int t = t0; t < t1; t++) g_row_expert[t] = e;
            off += padded;
        }
        g_nrows = off;
        for (int t = off / BM; t < ROW_TILES; t++) g_row_expert[t] = 0;
    }
    __syncthreads();

    // scatter
    for (int s = tid; s < 2 * T_TOKENS; s += 1024) {
        int e = s_e[s];
        int p = atomicAdd(&s_pos[e], 1);
        g_perm_tok[p] = s >> 1;
        g_perm_w[p]   = s_w[s];
    }
}

// ============================================================================
// Fused MoE GEMM kernel (one launch):
//   blocks [0, G1) : GEMM1 (+SiLU) -> g_h ; nTile-fastest (bid = rowTile*64+nTile)
//                    last act: threadfence + g_done[rowTile]++
//   blocks [G1, G1+G2) : GEMM2 -> out ; spins until g_done[rowTile]==64.
// All GEMM1 blocks precede all GEMM2 blocks in dispatch order -> no deadlock.
// ============================================================================
__global__ __launch_bounds__(NTHREADS, 1)
void k_moe(const float* __restrict__ W13f, const float* __restrict__ W2f,
           float* __restrict__ out) {
    extern __shared__ char dsm[];
    __shared__ int   toks[BM];
    __shared__ float wts[BM];

    const int tid  = threadIdx.x;
    const int bid  = blockIdx.x;
    const int lane = tid & 31, wid = tid >> 5;
    char* sb = (char*)(((uintptr_t)dsm + 127) & ~(uintptr_t)127);
    const uint32_t sbase = smem_u32(sb);

    const int lrow = lane & 15;
    const uint32_t xm   = (lane & 7) << 4;
    const uint32_t koff = (lane >> 4) * 16;

    if (bid < G1_BLOCKS) {
        // ==================== GEMM1 (+fused SiLU) ====================
        const int rowTile = bid >> 6, nTile = bid & 63;
        if (rowTile * BM >= g_nrows) return;
        const uint32_t ABASE = 0, BBASE = 3 * 16384;

        if (tid < BM) toks[tid] = g_perm_tok[rowTile * BM + tid];
        __syncthreads();

        const int e = g_row_expert[rowTile];
        const float* Wg = W13f + (size_t)e * N1 * HID + (size_t)(nTile * 64) * HID;

        auto fillA = [&](int st, int c) {
            const int k0 = c * KCH;
#pragma unroll
            for (int j = 0; j < 2; j++) {
                int idx = tid + j * NTHREADS;
                int row = idx >> 3, seg = idx & 7;
                int tok = toks[row];
                uint32_t dst = sbase + ABASE + st * 16384
                             + row * 128 + ((seg * 16) ^ ((row & 7) << 4));
                cp16(dst, g_Xh + (size_t)(tok < 0 ? 0 : tok) * HID + k0 + seg * 8,
                     tok < 0 ? 0 : 16);
            }
            CP_COMMIT();
        };

        float4 breg[4];
        auto ldgB = [&](int c) {
            const int k0 = c * KCH;
#pragma unroll
            for (int j = 0; j < 4; j++) {
                int idx = tid + j * NTHREADS;
                int row = idx >> 4, f4 = idx & 15;
                int grow = (row < 64) ? row : (INTER + row - 64);
                breg[j] = __ldg((const float4*)(Wg + (size_t)grow * HID + k0) + f4);
            }
        };
        auto stsB = [&](int st) {
#pragma unroll
            for (int j = 0; j < 4; j++) {
                int idx = tid + j * NTHREADS;
                int row = idx >> 4, f4 = idx & 15;
                int seg = f4 >> 1;
                uint32_t off = BBASE + st * 16384 + row * 128
                             + ((seg * 16) ^ ((row & 7) << 4)) + (f4 & 1) * 8;
                *(uint2*)(sb + off) = cvt4(breg[j]);
            }
        };

        ldgB(0);
        fillA(0, 0);
        fillA(1, 1);
        stsB(0);
        ldgB(1);

        // warp layout: 4 (m) x 4 (n); warp tile 32m x 16n per matrix
        const int wm = (wid & 3) * 32, wn = (wid >> 2) * 16;

        float cg[2][2][4], cu[2][2][4];
#pragma unroll
        for (int mt = 0; mt < 2; mt++)
#pragma unroll
            for (int nt = 0; nt < 2; nt++)
#pragma unroll
                for (int v = 0; v < 4; v++) { cg[mt][nt][v] = 0.f; cu[mt][nt][v] = 0.f; }

        for (int i = 0; i < NCHUNK; i++) {
            const int st = i & 1;
            if (i < NCHUNK - 1) { CP_WAIT1(); } else { CP_WAIT0(); }
            __syncthreads();
            if (i + 1 < NCHUNK) stsB(st ^ 1);
            if (i + 2 < NCHUNK) { ldgB(i + 2); fillA((i + 2) % 3, i + 2); }

            const uint32_t Ast = sbase + ABASE + (i % 3) * 16384;
            const uint32_t Bst = sbase + BBASE + st * 16384;
#pragma unroll
            for (int ks = 0; ks < 4; ks++) {
                const uint32_t kb = (uint32_t)(ks * 32 + koff) ^ xm;
                uint32_t a[2][4], bg[4], bu[4];
#pragma unroll
                for (int mt = 0; mt < 2; mt++)
                    LDSM4(a[mt][0], a[mt][1], a[mt][2], a[mt][3],
                          Ast + (wm + mt * 16 + lrow) * 128 + kb);
                LDSM4(bg[0], bg[1], bg[2], bg[3], Bst + (wn + lrow) * 128 + kb);
                LDSM4(bu[0], bu[1], bu[2], bu[3], Bst + 8192 + (wn + lrow) * 128 + kb);
#pragma unroll
                for (int mt = 0; mt < 2; mt++)
#pragma unroll
                    for (int nt = 0; nt < 2; nt++) {
                        mma_f16(cg[mt][nt], a[mt][0], a[mt][1], a[mt][2], a[mt][3],
                                bg[nt], bg[2 + nt]);
                        mma_f16(cu[mt][nt], a[mt][0], a[mt][1], a[mt][2], a[mt][3],
                                bu[nt], bu[2 + nt]);
                    }
            }
        }

        // epilogue: silu(gate)*up -> g_h (fp16)
        const int r0 = rowTile * BM + wm + lane / 4;
        const int cbase = nTile * 64 + wn + (lane % 4) * 2;
#pragma unroll
        for (int mt = 0; mt < 2; mt++) {
#pragma unroll
            for (int nt = 0; nt < 2; nt++) {
                __half* h0 = g_h + (size_t)(r0 + mt * 16) * INTER + cbase + nt * 8;
                __half* h1 = h0 + 8 * INTER;
                float g0 = cg[mt][nt][0], g1 = cg[mt][nt][1];
                float g2 = cg[mt][nt][2], g3 = cg[mt][nt][3];
                float v0 = g0 / (1.f + __expf(-g0)) * cu[mt][nt][0];
                float v1 = g1 / (1.f + __expf(-g1)) * cu[mt][nt][1];
                float v2 = g2 / (1.f + __expf(-g2)) * cu[mt][nt][2];
                float v3 = g3 / (1.f + __expf(-g3)) * cu[mt][nt][3];
                *(__half2*)h0 = __floats2half2_rn(v0, v1);
                *(__half2*)h1 = __floats2half2_rn(v2, v3);
            }
        }
        // publish
        __threadfence();
        __syncthreads();
        if (tid == 0) atomicAdd(&g_done[rowTile], 1);

    } else {
        // ==================== GEMM2 ====================
        const int b2 = bid - G1_BLOCKS;
        const int rowTile = b2 >> 5, nTile = b2 & 31;
        if (rowTile * BM >= g_nrows) return;
        const uint32_t ABASE = 0, BBASE = 3 * 16384;

        if (tid < BM) {
            toks[tid] = g_perm_tok[rowTile * BM + tid];
            wts[tid]  = g_perm_w[rowTile * BM + tid];
        }
        // wait for this rowTile's g_h to be complete
        if (tid == 0) {
            while (*(volatile int*)&g_done[rowTile] < 64) __nanosleep(128);
        }
        __syncthreads();
        __threadfence();

        const int e = g_row_expert[rowTile];
        const __half* A = g_h + (size_t)(rowTile * BM) * INTER;
        const float*  W = W2f + (size_t)e * HID * INTER + (size_t)(nTile * 128) * INTER;

        auto fillA = [&](int st, int c) {
            const int k0 = c * KCH;
#pragma unroll
            for (int j = 0; j < 2; j++) {
                int idx = tid + j * NTHREADS;
                int row = idx >> 3, seg = idx & 7;
                uint32_t dst = sbase + ABASE + st * 16384
                             + row * 128 + ((seg * 16) ^ ((row & 7) << 4));
                cp16(dst, A + (size_t)row * INTER + k0 + seg * 8, 16);
            }
            CP_COMMIT();
        };

        float4 breg[4];
        auto ldgB = [&](int c) {
            const int k0 = c * KCH;
#pragma unroll
            for (int j = 0; j < 4; j++) {
                int idx = tid + j * NTHREADS;
                int row = idx >> 4, f4 = idx & 15;
                breg[j] = __ldg((const float4*)(W + (size_t)row * INTER + k0) + f4);
            }
        };
        auto stsB = [&](int st) {
#pragma unroll
            for (int j = 0; j < 4; j++) {
                int idx = tid + j * NTHREADS;
                int row = idx >> 4, f4 = idx & 15;
                int seg = f4 >> 1;
                uint32_t off = BBASE + st * 16384 + row * 128
                             + ((seg * 16) ^ ((row & 7) << 4)) + (f4 & 1) * 8;
                *(uint2*)(sb + off) = cvt4(breg[j]);
            }
        };

        ldgB(0);
        fillA(0, 0);
        fillA(1, 1);
        stsB(0);
        ldgB(1);

        // warp layout: 4 (m) x 4 (n); warp tile 32m x 32n
        const int wm = (wid & 3) * 32, wn = (wid >> 2) * 32;

        float c[2][4][4];
#pragma unroll
        for (int mt = 0; mt < 2; mt++)
#pragma unroll
            for (int nt = 0; nt < 4; nt++)
#pragma unroll
                for (int v = 0; v < 4; v++) c[mt][nt][v] = 0.f;

        for (int i = 0; i < NCHUNK; i++) {
            const int st = i & 1;
            if (i < NCHUNK - 1) { CP_WAIT1(); } else { CP_WAIT0(); }
            __syncthreads();
            if (i + 1 < NCHUNK) stsB(st ^ 1);
            if (i + 2 < NCHUNK) { ldgB(i + 2); fillA((i + 2) % 3, i + 2); }

            const uint32_t Ast = sbase + ABASE + (i % 3) * 16384;
            const uint32_t Bst = sbase + BBASE + st * 16384;
#pragma unroll
            for (int ks = 0; ks < 4; ks++) {
                const uint32_t kb = (uint32_t)(ks * 32 + koff) ^ xm;
                uint32_t a[2][4], b[2][4];
#pragma unroll
                for (int mt = 0; mt < 2; mt++)
                    LDSM4(a[mt][0], a[mt][1], a[mt][2], a[mt][3],
                          Ast + (wm + mt * 16 + lrow) * 128 + kb);
#pragma unroll
                for (int g = 0; g < 2; g++)
                    LDSM4(b[g][0], b[g][1], b[g][2], b[g][3],
                          Bst + (wn + g * 16 + lrow) * 128 + kb);
#pragma unroll
                for (int mt = 0; mt < 2; mt++)
#pragma unroll
                    for (int nt = 0; nt < 4; nt++) {
                        int g = nt >> 1, s = nt & 1;
                        mma_f16(c[mt][nt], a[mt][0], a[mt][1], a[mt][2], a[mt][3],
                                b[g][s], b[g][2 + s]);
                    }
            }
        }

        // epilogue: weighted atomic combine (exactly 2 contributions per token;
        // 2-operand fp add onto zeroed buffer is order-invariant -> deterministic)
        const int cbase = nTile * 128 + wn + (lane % 4) * 2;
#pragma unroll
        for (int mt = 0; mt < 2; mt++) {
            const int rl0 = wm + mt * 16 + lane / 4;
            const int tok0 = toks[rl0],     tok1 = toks[rl0 + 8];
            const float w0 = wts[rl0],      w1 = wts[rl0 + 8];
            float* o0 = (tok0 >= 0) ? out + (size_t)tok0 * HID + cbase : nullptr;
            float* o1 = (tok1 >= 0) ? out + (size_t)tok1 * HID + cbase : nullptr;
#pragma unroll
            for (int nt = 0; nt < 4; nt++) {
                if (tok0 >= 0) {
                    atomicAdd(o0 + nt * 8,     w0 * c[mt][nt][0]);
                    atomicAdd(o0 + nt * 8 + 1, w0 * c[mt][nt][1]);
                }
                if (tok1 >= 0) {
                    atomicAdd(o1 + nt * 8,     w1 * c[mt][nt][2]);
                    atomicAdd(o1 + nt * 8 + 1, w1 * c[mt][nt][3]);
                }
            }
        }
    }
}

// ---------------- launch -----------------------------------------------------
extern "C" void kernel_launch(void* const* d_in, const int* in_sizes, int n_in,
                              void* d_out, int out_size) {
    const float* X      = (const float*)d_in[0];
    const float* logits = (const float*)d_in[1];
    const float* W13    = (const float*)d_in[2];
    const float* W2     = (const float*)d_in[3];
    float* out = (float*)d_out;

    const int smem = 5 * 16384 + 128;   // A 3 stages + B 2 stages
    cudaFuncSetAttribute(k_moe, cudaFuncAttributeMaxDynamicSharedMemorySize, smem);

    k_setup<<<1025, 1024>>>((float4*)out, (const float4*)X, logits);
    k_moe<<<G1_BLOCKS + G2_BLOCKS, NTHREADS, smem>>>(W13, W2, out);
}